// round 4
// baseline (speedup 1.0000x reference)
#include <cuda_runtime.h>
#include <cuda_fp16.h>
#include <cstdint>

// ============================================================================
// RPNHead on sm_103 WITHOUT tcgen05 (harness builds compute_103 PTX; tcgen05
// rejected by ptxas). Classic tensor path: mma.sync.m16n8k16 + cp.async +
// ldmatrix, fp16 inputs, fp32 accumulation.
//
// FIX vs round 3: B tiles are stored N-major with K contiguous ([n][k]),
// which requires NON-trans ldmatrix (same fragment class as A). The .trans
// variant delivered n-contiguous pairs and scrambled the B fragments.
// ============================================================================
#define DB 8
#define DH 128
#define DW 128
#define NPOS (DB*DH*DW)            // 131072
#define OFF_PROBS  3932160
#define OFF_DELTAS 7864320

// -------------------- device scratch ----------------------------------------
__device__ __align__(1024) __half g_xh[(size_t)NPOS*256];   // x fp16 [pos][c]
__device__ __align__(1024) __half g_sh[(size_t)NPOS*512];   // shared acts fp16
__device__ __align__(1024) __half g_wt[(size_t)512*2304];   // conv W [n][k], k=(kh*3+kw)*256+c
__device__ __align__(1024) __half g_wh[(size_t)128*512];    // head W [j][c], j>=90 zero

// -------------------- helpers ------------------------------------------------
__device__ __forceinline__ uint32_t smem_u32(const void* p) {
    uint32_t a;
    asm("{ .reg .u64 t; cvta.to.shared.u64 t, %1; cvt.u32.u64 %0, t; }"
        : "=r"(a) : "l"(p));
    return a;
}

#define CP_ASYNC16(dst, src, sz) \
    asm volatile("cp.async.cg.shared.global [%0], [%1], 16, %2;" \
        :: "r"((uint32_t)(dst)), "l"(src), "r"((int)(sz)) : "memory")
#define CP_COMMIT() asm volatile("cp.async.commit_group;" ::: "memory")
#define CP_WAIT1()  asm volatile("cp.async.wait_group 1;" ::: "memory")
#define CP_WAIT0()  asm volatile("cp.async.wait_group 0;" ::: "memory")

__device__ __forceinline__ void ldm4(uint32_t* f, uint32_t addr) {
    asm volatile("ldmatrix.sync.aligned.m8n8.x4.shared.b16 {%0,%1,%2,%3}, [%4];"
        : "=r"(f[0]), "=r"(f[1]), "=r"(f[2]), "=r"(f[3]) : "r"(addr));
}
__device__ __forceinline__ void mma16816(float* c, const uint32_t* a,
                                         uint32_t b0, uint32_t b1) {
    asm volatile("mma.sync.aligned.m16n8k16.row.col.f32.f16.f16.f32 "
        "{%0,%1,%2,%3}, {%4,%5,%6,%7}, {%8,%9}, {%0,%1,%2,%3};"
        : "+f"(c[0]), "+f"(c[1]), "+f"(c[2]), "+f"(c[3])
        : "r"(a[0]), "r"(a[1]), "r"(a[2]), "r"(a[3]), "r"(b0), "r"(b1));
}

// ============================================================================
// Kernel 1: x fp32 -> fp16
// ============================================================================
__global__ void cvt_x_kernel(const float4* __restrict__ in) {
    int i = blockIdx.x * 256 + threadIdx.x;
    float4 f = in[i];
    __half2 a = __floats2half2_rn(f.x, f.y);
    __half2 b = __floats2half2_rn(f.z, f.w);
    uint2 v;
    v.x = *reinterpret_cast<uint32_t*>(&a);
    v.y = *reinterpret_cast<uint32_t*>(&b);
    reinterpret_cast<uint2*>(g_xh)[i] = v;
}

// ============================================================================
// Kernel 2: weight repack (K-major conv weights; padded head weight matrix)
// ============================================================================
__global__ void cvt_w_kernel(const float* __restrict__ ws, const float* __restrict__ wc,
                             const float* __restrict__ wr) {
    int k = blockIdx.x;          // 0..2303
    int n = threadIdx.x;         // 0..511
    g_wt[(size_t)n * 2304 + k] = __float2half(ws[(size_t)k * 512 + n]);
    if (k < 128) {
        int j = k, c = n;
        float v = 0.0f;
        if (j < 30)      v = wc[c * 30 + j];
        else if (j < 90) v = wr[c * 60 + (j - 30)];
        g_wh[(size_t)j * 512 + c] = __float2half(v);
    }
}

// ============================================================================
// Kernel 3: conv 3x3 (256->512) + bias + relu6, implicit GEMM via mma.sync.
// grid = 2048: blockIdx>>1 = (b*128+h), blockIdx&1 = n-half (256 wide).
// 512 threads = 16 warps, warp tile 64x32, CTA tile 128(M=w)x256(N), K-chunk 64.
// ============================================================================
#define CV_A(buf)  ((buf) * 49152u)
#define CV_B(buf)  ((buf) * 49152u + 16384u)
#define CV_BIAS    98304u
#define CV_SMEM    99328
#define CV_NCH     36

__global__ void __launch_bounds__(512, 1) conv_kernel(const float* __restrict__ bias)
{
    extern __shared__ char sm[];
    const uint32_t sb = smem_u32(sm);
    const int tid = threadIdx.x;
    const int rowid = blockIdx.x >> 1;
    const int n0 = (blockIdx.x & 1) << 8;
    const int b = rowid >> 7, h = rowid & 127;

    float* sbias = reinterpret_cast<float*>(sm + CV_BIAS);
    if (tid < 256) sbias[tid] = bias[n0 + tid];

    // per-thread load geometry
    const int rowA = tid >> 2;            // A: 2 16B-groups, one half-row
    const int kgA0 = (tid * 2) & 7;
    const int rowB = tid >> 1;            // B: 4 16B-groups, one half-row
    const int kgB0 = (tid * 4) & 7;
    const uint32_t swA = (uint32_t)(rowA & 7);
    const uint32_t swB = (uint32_t)(rowB & 7);

    // warp geometry
    const int w = tid >> 5, l = tid & 31;
    const int wm = (w >> 3) * 64, wn = (w & 7) * 32;
    const int lrow = l & 15, hi = l >> 4;
    const uint32_t swL = (uint32_t)(lrow & 7);
    uint32_t aRow[4], bRow[2];
    #pragma unroll
    for (int mt = 0; mt < 4; ++mt) aRow[mt] = (uint32_t)((wm + mt * 16 + lrow) * 128);
    #pragma unroll
    for (int nt = 0; nt < 2; ++nt) bRow[nt] = (uint32_t)((wn + nt * 16 + lrow) * 128);

    float acc[4][4][4];
    #pragma unroll
    for (int mt = 0; mt < 4; ++mt)
        #pragma unroll
        for (int n8 = 0; n8 < 4; ++n8)
            #pragma unroll
            for (int e = 0; e < 4; ++e) acc[mt][n8][e] = 0.0f;

    auto load_chunk = [&](int q, int buf) {
        const int tap = q >> 2, ci = q & 3;
        const int kh = tap / 3, kw = tap - kh * 3;
        const int hh = h + kh - 1;
        const int ww = rowA + kw - 1;
        const bool av = (hh >= 0) && (hh < 128) && (ww >= 0) && (ww < 128);
        const int hc = min(max(hh, 0), 127), wc_ = min(max(ww, 0), 127);
        const char* srcA = reinterpret_cast<const char*>(
            g_xh + ((size_t)((b * 128 + hc) * 128 + wc_) * 256 + ci * 64));
        const uint32_t Ab = sb + CV_A(buf), Bb = sb + CV_B(buf);
        #pragma unroll
        for (int i = 0; i < 2; ++i) {
            const int kg = kgA0 + i;
            CP_ASYNC16(Ab + (uint32_t)rowA * 128 + (((uint32_t)kg ^ swA) << 4),
                       srcA + kg * 16, av ? 16 : 0);
        }
        const char* srcB = reinterpret_cast<const char*>(
            g_wt + (size_t)(n0 + rowB) * 2304 + q * 64);
        #pragma unroll
        for (int i = 0; i < 4; ++i) {
            const int kg = kgB0 + i;
            CP_ASYNC16(Bb + (uint32_t)rowB * 128 + (((uint32_t)kg ^ swB) << 4),
                       srcB + kg * 16, 16);
        }
    };

    load_chunk(0, 0);
    CP_COMMIT();

    #pragma unroll 1
    for (int q = 0; q < CV_NCH; ++q) {
        if (q + 1 < CV_NCH) {
            load_chunk(q + 1, (q + 1) & 1);
            CP_COMMIT();
            CP_WAIT1();
        } else {
            CP_WAIT0();
        }
        __syncthreads();

        const uint32_t Ab = sb + CV_A(q & 1), Bb = sb + CV_B(q & 1);
        #pragma unroll
        for (int ks = 0; ks < 4; ++ks) {
            const uint32_t col = (((uint32_t)(ks * 2 + hi)) ^ swL) << 4;
            uint32_t af[4][4], bf[2][4];
            #pragma unroll
            for (int mt = 0; mt < 4; ++mt) ldm4(af[mt], Ab + aRow[mt] + col);
            #pragma unroll
            for (int nt = 0; nt < 2; ++nt) ldm4(bf[nt], Bb + bRow[nt] + col);
            #pragma unroll
            for (int mt = 0; mt < 4; ++mt)
                #pragma unroll
                for (int n8 = 0; n8 < 4; ++n8)
                    mma16816(acc[mt][n8], af[mt], bf[n8 >> 1][n8 & 1], bf[n8 >> 1][(n8 & 1) + 2]);
        }
        __syncthreads();
    }

    // epilogue: bias + relu6 -> fp16 scratch
    const int qrow = l >> 2, qcol = (l & 3) * 2;
    #pragma unroll
    for (int mt = 0; mt < 4; ++mt) {
        #pragma unroll
        for (int n8 = 0; n8 < 4; ++n8) {
            const int ch = wn + n8 * 8 + qcol;
            const float b0 = sbias[ch], b1 = sbias[ch + 1];
            #pragma unroll
            for (int hlf = 0; hlf < 2; ++hlf) {
                const int m = wm + mt * 16 + qrow + hlf * 8;
                float v0 = acc[mt][n8][2 * hlf]     + b0;
                float v1 = acc[mt][n8][2 * hlf + 1] + b1;
                v0 = fminf(fmaxf(v0, 0.0f), 6.0f);
                v1 = fminf(fmaxf(v1, 0.0f), 6.0f);
                const size_t pos = (size_t)rowid * 128 + m;
                *reinterpret_cast<__half2*>(g_sh + pos * 512 + n0 + ch) =
                    __floats2half2_rn(v0, v1);
            }
        }
    }
}

// ============================================================================
// Kernel 4: head GEMM M=128/N=128(96 used)/K=512 + bias + softmax + writes.
// grid = 1024, 256 threads = 8 warps (2m x 4n), warp tile 64x32. 8 K-chunks.
// ============================================================================
#define HD_A(buf)  ((buf) * 32768u)
#define HD_B(buf)  ((buf) * 32768u + 16384u)
#define HD_BIAS    65536u
#define HD_SMEM    66048
#define HD_NCH     8

__global__ void __launch_bounds__(256, 1) head_kernel(const float* __restrict__ bc,
                                                      const float* __restrict__ br,
                                                      float* __restrict__ out)
{
    extern __shared__ char sm[];
    const uint32_t sb = smem_u32(sm);
    const int tid = threadIdx.x;
    const size_t pos0 = (size_t)blockIdx.x * 128;

    float* hb = reinterpret_cast<float*>(sm + HD_BIAS);
    if (tid < 128)
        hb[tid] = (tid < 30) ? bc[tid] : (tid < 90 ? br[tid - 30] : 0.0f);

    const int rowT = tid >> 1;            // both A and B: 4 groups, one half-row
    const int kg0 = (tid * 4) & 7;
    const uint32_t swT = (uint32_t)(rowT & 7);

    const int w = tid >> 5, l = tid & 31;
    const int wm = (w >> 2) * 64, wn = (w & 3) * 32;
    const int lrow = l & 15, hi = l >> 4;
    const uint32_t swL = (uint32_t)(lrow & 7);
    uint32_t aRow[4], bRow[2];
    #pragma unroll
    for (int mt = 0; mt < 4; ++mt) aRow[mt] = (uint32_t)((wm + mt * 16 + lrow) * 128);
    #pragma unroll
    for (int nt = 0; nt < 2; ++nt) bRow[nt] = (uint32_t)((wn + nt * 16 + lrow) * 128);

    float acc[4][4][4];
    #pragma unroll
    for (int mt = 0; mt < 4; ++mt)
        #pragma unroll
        for (int n8 = 0; n8 < 4; ++n8)
            #pragma unroll
            for (int e = 0; e < 4; ++e) acc[mt][n8][e] = 0.0f;

    auto load_chunk = [&](int q, int buf) {
        const uint32_t Ab = sb + HD_A(buf), Bb = sb + HD_B(buf);
        const char* srcA = reinterpret_cast<const char*>(
            g_sh + (pos0 + rowT) * 512 + q * 64);
        const char* srcB = reinterpret_cast<const char*>(
            g_wh + (size_t)rowT * 512 + q * 64);
        #pragma unroll
        for (int i = 0; i < 4; ++i) {
            const int kg = kg0 + i;
            const uint32_t off = (uint32_t)rowT * 128 + (((uint32_t)kg ^ swT) << 4);
            CP_ASYNC16(Ab + off, srcA + kg * 16, 16);
            CP_ASYNC16(Bb + off, srcB + kg * 16, 16);
        }
    };

    load_chunk(0, 0);
    CP_COMMIT();

    #pragma unroll 1
    for (int q = 0; q < HD_NCH; ++q) {
        if (q + 1 < HD_NCH) {
            load_chunk(q + 1, (q + 1) & 1);
            CP_COMMIT();
            CP_WAIT1();
        } else {
            CP_WAIT0();
        }
        __syncthreads();

        const uint32_t Ab = sb + HD_A(q & 1), Bb = sb + HD_B(q & 1);
        #pragma unroll
        for (int ks = 0; ks < 4; ++ks) {
            const uint32_t col = (((uint32_t)(ks * 2 + hi)) ^ swL) << 4;
            uint32_t af[4][4], bf[2][4];
            #pragma unroll
            for (int mt = 0; mt < 4; ++mt) ldm4(af[mt], Ab + aRow[mt] + col);
            #pragma unroll
            for (int nt = 0; nt < 2; ++nt) ldm4(bf[nt], Bb + bRow[nt] + col);
            #pragma unroll
            for (int mt = 0; mt < 4; ++mt)
                #pragma unroll
                for (int n8 = 0; n8 < 4; ++n8)
                    mma16816(acc[mt][n8], af[mt], bf[n8 >> 1][n8 & 1], bf[n8 >> 1][(n8 & 1) + 2]);
        }
        __syncthreads();
    }

    // epilogue: bias, softmax over (even, odd) channel pairs, scatter outputs
    const int qrow = l >> 2, qcol = (l & 3) * 2;
    #pragma unroll
    for (int mt = 0; mt < 4; ++mt) {
        #pragma unroll
        for (int n8 = 0; n8 < 4; ++n8) {
            const int ch = wn + n8 * 8 + qcol;         // even, 0..126
            if (ch >= 90) continue;
            const float b0 = hb[ch], b1 = hb[ch + 1];
            #pragma unroll
            for (int hlf = 0; hlf < 2; ++hlf) {
                const int m = wm + mt * 16 + qrow + hlf * 8;
                const size_t pos = pos0 + m;
                const float v0 = acc[mt][n8][2 * hlf]     + b0;
                const float v1 = acc[mt][n8][2 * hlf + 1] + b1;
                if (ch < 30) {
                    *reinterpret_cast<float2*>(out + pos * 30 + ch) = make_float2(v0, v1);
                    const float mx = fmaxf(v0, v1);
                    const float e0 = __expf(v0 - mx), e1 = __expf(v1 - mx);
                    const float inv = 1.0f / (e0 + e1);
                    *reinterpret_cast<float2*>(out + OFF_PROBS + pos * 30 + ch) =
                        make_float2(e0 * inv, e1 * inv);
                } else {
                    *reinterpret_cast<float2*>(out + OFF_DELTAS + pos * 60 + (ch - 30)) =
                        make_float2(v0, v1);
                }
            }
        }
    }
}

// ============================================================================
// Launch
// ============================================================================
extern "C" void kernel_launch(void* const* d_in, const int* in_sizes, int n_in,
                              void* d_out, int out_size) {
    const float* x  = (const float*)d_in[0];
    const float* ws = (const float*)d_in[1];
    const float* bs = (const float*)d_in[2];
    const float* wc = (const float*)d_in[3];
    const float* bc = (const float*)d_in[4];
    const float* wr = (const float*)d_in[5];
    const float* br = (const float*)d_in[6];
    float* out = (float*)d_out;

    cudaFuncSetAttribute(conv_kernel, cudaFuncAttributeMaxDynamicSharedMemorySize, CV_SMEM);
    cudaFuncSetAttribute(head_kernel, cudaFuncAttributeMaxDynamicSharedMemorySize, HD_SMEM);

    cvt_x_kernel<<<32768, 256>>>(reinterpret_cast<const float4*>(x));
    cvt_w_kernel<<<2304, 512>>>(ws, wc, wr);
    conv_kernel<<<2048, 512, CV_SMEM>>>(bs);
    head_kernel<<<1024, 256, HD_SMEM>>>(bc, br, out);
}